// round 5
// baseline (speedup 1.0000x reference)
#include <cuda_runtime.h>
#include <math.h>
#include <stdint.h>

#define NTOK 8192
#define DM 1024
#define DF 4096
#define NE 8
#define BM 128
#define BN 64
#define BKB 128                    /* K elems (=bytes) per chunk */
#define MAXROWS (NTOK*2 + NE*BM)   /* 17408 */
#define MT (MAXROWS/BM)            /* 136 */

// smem stage: A hi 16K, A lo 16K, B hi 8K, B lo 8K = 48KB; 3 stages
#define AH_OFF 0
#define AL_OFF 16384
#define BH_OFF 32768
#define BL_OFF 40960
#define ST_SIZE 49152
#define SMEM_BYTES (1024 + 3*ST_SIZE)   /* 148480 */

// ---------------- scratch (device globals: allocation-free) ----------------
__device__ __align__(16) int8_t g_xq_h[(size_t)MAXROWS * DM];
__device__ __align__(16) int8_t g_xq_l[(size_t)MAXROWS * DM];
__device__ __align__(16) float  g_h[(size_t)MAXROWS * DF];
__device__ __align__(16) int8_t g_hq_h[(size_t)MAXROWS * DF];
__device__ __align__(16) int8_t g_hq_l[(size_t)MAXROWS * DF];
__device__ __align__(16) int8_t g_w1q_h[(size_t)NE * DF * DM];
__device__ __align__(16) int8_t g_w1q_l[(size_t)NE * DF * DM];
__device__ __align__(16) int8_t g_w2q_h[(size_t)NE * DM * DF];
__device__ __align__(16) int8_t g_w2q_l[(size_t)NE * DM * DF];
__device__ __align__(16) float  g_y[(size_t)MAXROWS * DM];
__device__ float g_sxa[MAXROWS];      // x row scales
__device__ float g_sha[MAXROWS];      // h row scales
__device__ float g_w1max[NE];
__device__ float g_w2max[NE];
__device__ int   g_atok[MAXROWS];
__device__ float g_aw[MAXROWS];
__device__ int   g_tokslot[NTOK * 2];
__device__ int   g_t2e[NTOK * 2];
__device__ float g_t2w[NTOK * 2];
__device__ int   g_cnt[NE];
__device__ int   g_fill[NE];
__device__ int   g_off[NE + 1];

// ---------------- helpers ----------------
__device__ __forceinline__ uint32_t smem_u32(const void* p) {
    uint32_t a;
    asm("{ .reg .u64 t; cvta.to.shared.u64 t, %1; cvt.u32.u64 %0, t; }" : "=r"(a) : "l"(p));
    return a;
}
#define SWZ(x) ((uint32_t)(x) ^ ((((uint32_t)(x)) >> 3) & 0x70))

__device__ __forceinline__ void cp16(uint32_t dst, const void* src) {
    asm volatile("cp.async.cg.shared.global [%0], [%1], 16;" :: "r"(dst), "l"(src));
}
#define CP_COMMIT() asm volatile("cp.async.commit_group;" ::: "memory")
#define CP_WAIT1()  asm volatile("cp.async.wait_group 1;" ::: "memory")
#define CP_WAIT0()  asm volatile("cp.async.wait_group 0;" ::: "memory")

__device__ __forceinline__ void ldm4(uint32_t* r, uint32_t addr) {
    asm volatile("ldmatrix.sync.aligned.m8n8.x4.shared.b16 {%0,%1,%2,%3}, [%4];"
        : "=r"(r[0]), "=r"(r[1]), "=r"(r[2]), "=r"(r[3]) : "r"(addr));
}
__device__ __forceinline__ void imma16832(int* c, const uint32_t* a, uint32_t b0, uint32_t b1) {
    asm volatile("mma.sync.aligned.m16n8k32.row.col.s32.s8.s8.s32 "
        "{%0,%1,%2,%3}, {%4,%5,%6,%7}, {%8,%9}, {%0,%1,%2,%3};"
        : "+r"(c[0]), "+r"(c[1]), "+r"(c[2]), "+r"(c[3])
        : "r"(a[0]), "r"(a[1]), "r"(a[2]), "r"(a[3]), "r"(b0), "r"(b1));
}

// 15-bit limb split: q15 in [-16256,16256] -> hi in [-127,127], lo in [-64,64]
__device__ __forceinline__ void limbs(float v, float inv, int8_t& hi, int8_t& lo) {
    int q = (int)lrintf(v * inv);
    q = max(-16256, min(16256, q));
    int h = ((q + 16448) >> 7) - 128;
    hi = (int8_t)h;
    lo = (int8_t)(q - (h << 7));
}

// ---------------- init ----------------
__global__ void k_init() {
    int i = blockIdx.x * blockDim.x + threadIdx.x;
    if (i < MAXROWS) g_atok[i] = -1;
    if (i < NE) { g_cnt[i] = 0; g_fill[i] = 0; g_w1max[i] = 0.f; g_w2max[i] = 0.f; }
}

// ---------------- gating ----------------
__global__ __launch_bounds__(256) void k_gate(const float* __restrict__ x,
                                              const float* __restrict__ gw,
                                              const float* __restrict__ gb) {
    __shared__ float sgw[DM * NE];
    int tid = threadIdx.x;
    for (int i = tid; i < DM * NE; i += 256) sgw[i] = gw[i];
    __syncthreads();
    int warp = tid >> 5, lane = tid & 31;
    int t = blockIdx.x * 8 + warp;
    const float* xr = x + (size_t)t * DM;
    float acc[NE];
#pragma unroll
    for (int e = 0; e < NE; e++) acc[e] = 0.f;
    for (int d = lane; d < DM; d += 32) {
        float xv = xr[d];
#pragma unroll
        for (int e = 0; e < NE; e++) acc[e] = fmaf(xv, sgw[d * NE + e], acc[e]);
    }
#pragma unroll
    for (int off = 16; off; off >>= 1)
#pragma unroll
        for (int e = 0; e < NE; e++) acc[e] += __shfl_xor_sync(0xFFFFFFFFu, acc[e], off);
    if (lane == 0) {
        float lg[NE], m = -1e30f;
#pragma unroll
        for (int e = 0; e < NE; e++) { lg[e] = acc[e] + gb[e]; m = fmaxf(m, lg[e]); }
        float ex[NE], s = 0.f;
#pragma unroll
        for (int e = 0; e < NE; e++) { ex[e] = expf(lg[e] - m); s += ex[e]; }
        int e0 = 0;
#pragma unroll
        for (int e = 1; e < NE; e++) if (ex[e] > ex[e0]) e0 = e;
        int e1 = (e0 == 0) ? 1 : 0;
#pragma unroll
        for (int e = 0; e < NE; e++) if (e != e0 && ex[e] > ex[e1]) e1 = e;
        float inv = 1.f / s;
        g_t2e[2 * t] = e0;     g_t2w[2 * t] = ex[e0] * inv;
        g_t2e[2 * t + 1] = e1; g_t2w[2 * t + 1] = ex[e1] * inv;
        atomicAdd(&g_cnt[e0], 1);
        atomicAdd(&g_cnt[e1], 1);
    }
}

__global__ void k_off() {
    g_off[0] = 0;
    for (int e = 0; e < NE; e++)
        g_off[e + 1] = g_off[e] + (((g_cnt[e] + BM - 1) / BM) * BM);
}

__global__ void k_scatter() {
    int t = blockIdx.x * blockDim.x + threadIdx.x;
    if (t >= NTOK) return;
#pragma unroll
    for (int r = 0; r < 2; r++) {
        int e = g_t2e[2 * t + r];
        int p = atomicAdd(&g_fill[e], 1);
        int s = g_off[e] + p;
        g_atok[s] = t;
        g_aw[s] = g_t2w[2 * t + r];
        g_tokslot[2 * t + r] = s;
    }
}

// ---------------- gather + quantize activations (per-row scale) ----------------
__global__ __launch_bounds__(256) void k_xquant(const float* __restrict__ x) {
    __shared__ float smax[8];
    int slot = blockIdx.x;
    int tok = g_atok[slot];
    int tid = threadIdx.x, wid = tid >> 5, lane = tid & 31;
    const float* xr = (tok >= 0) ? (x + (size_t)tok * DM) : 0;
    float v[4];
#pragma unroll
    for (int j = 0; j < 4; j++) v[j] = xr ? xr[tid + j * 256] : 0.f;
    float m = 0.f;
#pragma unroll
    for (int j = 0; j < 4; j++) m = fmaxf(m, fabsf(v[j]));
#pragma unroll
    for (int off = 16; off; off >>= 1) m = fmaxf(m, __shfl_xor_sync(0xFFFFFFFFu, m, off));
    if (lane == 0) smax[wid] = m;
    __syncthreads();
    m = smax[0];
#pragma unroll
    for (int w = 1; w < 8; w++) m = fmaxf(m, smax[w]);
    m = fmaxf(m, 1e-20f);
    float inv = 16256.f / m;
    if (tid == 0) g_sxa[slot] = m * (1.f / 16256.f);
#pragma unroll
    for (int j = 0; j < 4; j++) {
        int8_t hi, lo;
        limbs(v[j], inv, hi, lo);
        g_xq_h[(size_t)slot * DM + tid + j * 256] = hi;
        g_xq_l[(size_t)slot * DM + tid + j * 256] = lo;
    }
}

// ---------------- per-expert weight absmax ----------------
template <bool W1>
__global__ __launch_bounds__(256) void k_wmax(const float* __restrict__ w) {
    __shared__ float smax[8];
    int e = blockIdx.y;
    int tid = threadIdx.x, wid = tid >> 5, lane = tid & 31;
    const float* we = w + (size_t)e * DM * DF;
    float m = 0.f;
    for (size_t i = blockIdx.x * 256 + tid; i < (size_t)DM * DF; i += 256u * 256u)
        m = fmaxf(m, fabsf(we[i]));
#pragma unroll
    for (int off = 16; off; off >>= 1) m = fmaxf(m, __shfl_xor_sync(0xFFFFFFFFu, m, off));
    if (lane == 0) smax[wid] = m;
    __syncthreads();
    if (tid == 0) {
        float mm = smax[0];
#pragma unroll
        for (int w2 = 1; w2 < 8; w2++) mm = fmaxf(mm, smax[w2]);
        atomicMax((int*)(W1 ? &g_w1max[e] : &g_w2max[e]), __float_as_int(mm));
    }
}

// ---------------- transpose + quantize weights ----------------
// src [e][K][N] -> limbs [e][N][K] with per-expert scale
template <int K, int N, bool W1>
__global__ __launch_bounds__(256) void k_wquant(const float* __restrict__ w) {
    __shared__ float tile[32][33];
    int e = blockIdx.z;
    int n0 = blockIdx.x * 32, k0 = blockIdx.y * 32;
    int tx = threadIdx.x, ty = threadIdx.y;
    const float* we = w + (size_t)e * K * N;
    float mx = fmaxf(W1 ? g_w1max[e] : g_w2max[e], 1e-20f);
    float inv = 16256.f / mx;
    for (int i = ty; i < 32; i += 8)
        tile[i][tx] = we[(size_t)(k0 + i) * N + n0 + tx];
    __syncthreads();
    int8_t* ohe = (W1 ? g_w1q_h : g_w2q_h) + (size_t)e * N * K;
    int8_t* ole = (W1 ? g_w1q_l : g_w2q_l) + (size_t)e * N * K;
    for (int i = ty; i < 32; i += 8) {
        int8_t hi, lo;
        limbs(tile[tx][i], inv, hi, lo);
        size_t o = (size_t)(n0 + i) * K + k0 + tx;
        ohe[o] = hi;
        ole[o] = lo;
    }
}

// ================= IMMA mainloop =================
// A [BM][K] row-major int8 limbs, B [BN][K] n-major int8 limbs.
// 8 warps: 2x4 grid, warp tile 64x16. 3-stage cp.async pipeline.
struct IAcc { int hh[4][2][4]; int xx[4][2][4]; };

__device__ __forceinline__ void imma_mainloop(
    uint32_t sb, IAcc& A,
    const int8_t* Ah, const int8_t* Al, int astride,
    const int8_t* Bh, const int8_t* Bl, int bstride,
    int NC, int tid)
{
    int wid = tid >> 5, L = tid & 31;
    int wm = wid & 1, wn = wid >> 1;

    int afr = tid >> 1, ahb = (tid & 1) * 64;   // A: 128 rows, 64B halves
    int bfr = tid >> 2, bqb = (tid & 3) * 32;   // B: 64 rows, 32B quarters

    auto fill = [&](int s, int c) {
        uint32_t st = sb + s * ST_SIZE;
        const char* pah = (const char*)(Ah + (size_t)afr * astride + c * BKB) + ahb;
        const char* pal = (const char*)(Al + (size_t)afr * astride + c * BKB) + ahb;
        uint32_t ar = afr * 128 + ahb;
#pragma unroll
        for (int j = 0; j < 4; j++) {
            uint32_t o = SWZ(ar + j * 16);
            cp16(st + AH_OFF + o, pah + j * 16);
            cp16(st + AL_OFF + o, pal + j * 16);
        }
        const char* pbh = (const char*)(Bh + (size_t)bfr * bstride + c * BKB) + bqb;
        const char* pbl = (const char*)(Bl + (size_t)bfr * bstride + c * BKB) + bqb;
        uint32_t br = bfr * 128 + bqb;
#pragma unroll
        for (int j = 0; j < 2; j++) {
            uint32_t o = SWZ(br + j * 16);
            cp16(st + BH_OFF + o, pbh + j * 16);
            cp16(st + BL_OFF + o, pbl + j * 16);
        }
    };

    fill(0, 0); CP_COMMIT();
    fill(1, 1); CP_COMMIT();

    int lrow = L & 15;
    int lkb = (L >> 4) * 16;

    for (int c = 0; c < NC; c++) {
        if (c + 1 < NC) CP_WAIT1(); else CP_WAIT0();
        __syncthreads();
        // fill 2 ahead into stage (c+2)%3 (last used by chunk c-1, done by barrier)
        if (c + 2 < NC) { fill((c + 2) % 3, c + 2); CP_COMMIT(); }
        uint32_t st = sb + (c % 3) * ST_SIZE;

#pragma unroll
        for (int ks = 0; ks < 4; ks++) {
            uint32_t kb = ks * 32 + lkb;
            uint32_t ah[4][4], al[4][4], bh[4], bl[4];
#pragma unroll
            for (int mi = 0; mi < 4; mi++) {
                uint32_t ro = (wm * 64 + mi * 16 + lrow) * 128 + kb;
                ldm4(ah[mi], st + AH_OFF + SWZ(ro));
                ldm4(al[mi], st + AL_OFF + SWZ(ro));
            }
            {
                uint32_t ro = (wn * 16 + lrow) * 128 + kb;
                ldm4(bh, st + BH_OFF + SWZ(ro));
                ldm4(bl, st + BL_OFF + SWZ(ro));
            }
#pragma unroll
            for (int mi = 0; mi < 4; mi++)
#pragma unroll
                for (int nj = 0; nj < 2; nj++) {
                    imma16832(A.hh[mi][nj], ah[mi], bh[nj], bh[nj + 2]);
                    imma16832(A.xx[mi][nj], ah[mi], bl[nj], bl[nj + 2]);
                    imma16832(A.xx[mi][nj], al[mi], bh[nj], bh[nj + 2]);
                }
        }
    }
}

// ---------------- GEMM1: h = relu(x @ w1 + b1) -> fp32 ----------------
__global__ __launch_bounds__(256, 1) void k_imma1(const float* __restrict__ b1) {
    extern __shared__ char smem[];
    int row0 = blockIdx.y * BM;
    if (row0 >= g_off[NE]) return;
    int e = 0;
#pragma unroll
    for (int i = 0; i < NE - 1; i++) if (g_off[i + 1] <= row0) e = i + 1;
    int col0 = blockIdx.x * BN;
    uint32_t sb = (smem_u32(smem) + 1023) & ~1023u;
    int tid = threadIdx.x;

    IAcc A;
#pragma unroll
    for (int i = 0; i < 4; i++)
#pragma unroll
        for (int j = 0; j < 2; j++)
#pragma unroll
            for (int k = 0; k < 4; k++) { A.hh[i][j][k] = 0; A.xx[i][j][k] = 0; }

    imma_mainloop(sb, A,
                  g_xq_h + (size_t)row0 * DM, g_xq_l + (size_t)row0 * DM, DM,
                  g_w1q_h + (size_t)e * DF * DM + (size_t)col0 * DM,
                  g_w1q_l + (size_t)e * DF * DM + (size_t)col0 * DM, DM,
                  DM / BKB, tid);

    int wid = tid >> 5, L = tid & 31;
    int wm = wid & 1, wn = wid >> 1;
    const float* b1e = b1 + (size_t)e * DF;
    float sw = g_w1max[e] * (1.f / 16256.f);
#pragma unroll
    for (int mi = 0; mi < 4; mi++) {
        int r0 = row0 + wm * 64 + mi * 16 + (L >> 2);
        float sa0 = g_sxa[r0] * sw;
        float sa1 = g_sxa[r0 + 8] * sw;
#pragma unroll
        for (int nj = 0; nj < 2; nj++) {
            int col = col0 + wn * 16 + nj * 8 + (L & 3) * 2;
            float bb0 = b1e[col], bb1 = b1e[col + 1];
            const int* hh = A.hh[mi][nj];
            const int* xx = A.xx[mi][nj];
            float2 v0, v1;
            v0.x = fmaxf((16384.f * hh[0] + 128.f * xx[0]) * sa0 + bb0, 0.f);
            v0.y = fmaxf((16384.f * hh[1] + 128.f * xx[1]) * sa0 + bb1, 0.f);
            v1.x = fmaxf((16384.f * hh[2] + 128.f * xx[2]) * sa1 + bb0, 0.f);
            v1.y = fmaxf((16384.f * hh[3] + 128.f * xx[3]) * sa1 + bb1, 0.f);
            *(float2*)(g_h + (size_t)r0 * DF + col) = v0;
            *(float2*)(g_h + (size_t)(r0 + 8) * DF + col) = v1;
        }
    }
}

// ---------------- quantize h rows ----------------
__global__ __launch_bounds__(256) void k_hquant() {
    __shared__ float smax[8];
    int row = blockIdx.x;
    int tid = threadIdx.x, wid = tid >> 5, lane = tid & 31;
    const float* hr = g_h + (size_t)row * DF;
    float v[16];
#pragma unroll
    for (int j = 0; j < 16; j++) v[j] = hr[tid + j * 256];
    float m = 0.f;
#pragma unroll
    for (int j = 0; j < 16; j++) m = fmaxf(m, fabsf(v[j]));
#pragma unroll
    for (int off = 16; off; off >>= 1) m = fmaxf(m, __shfl_xor_sync(0xFFFFFFFFu, m, off));
    if (lane == 0) smax[wid] = m;
    __syncthreads();
    m = smax[0];
#pragma unroll
    for (int w = 1; w < 8; w++) m = fmaxf(m, smax[w]);
    m = fmaxf(m, 1e-20f);
    float inv = 16256.f / m;
    if (tid == 0) g_sha[row] = m * (1.f / 16256.f);
#pragma unroll
    for (int j = 0; j < 16; j++) {
        int8_t hi, lo;
        limbs(v[j], inv, hi, lo);
        g_hq_h[(size_t)row * DF + tid + j * 256] = hi;
        g_hq_l[(size_t)row * DF + tid + j * 256] = lo;
    }
}

// ---------------- GEMM2: y = (h @ w2 + b2) * gate ----------------
__global__ __launch_bounds__(256, 1) void k_imma2(const float* __restrict__ b2) {
    extern __shared__ char smem[];
    int row0 = blockIdx.y * BM;
    if (row0 >= g_off[NE]) return;
    int e = 0;
#pragma unroll
    for (int i = 0; i < NE - 1; i++) if (g_off[i + 1] <= row0) e = i + 1;
    int col0 = blockIdx.x * BN;
    uint32_t sb = (smem_u32(smem) + 1023) & ~1023u;
    int tid = threadIdx.x;

    IAcc A;
#pragma unroll
    for (int i = 0; i < 4; i++)
#pragma unroll
        for (int j = 0; j < 2; j++)
#pragma unroll
            for (int k = 0; k < 4; k++) { A.hh[i][j][k] = 0; A.xx[i][j][k] = 0; }

    imma_mainloop(sb, A,
                  g_hq_h + (size_t)row0 * DF, g_hq_l + (size_t)row0 * DF, DF,
                  g_w2q_h + (size_t)e * DM * DF + (size_t)col0 * DF,
                  g_w2q_l + (size_t)e * DM * DF + (size_t)col0 * DF, DF,
                  DF / BKB, tid);

    int wid = tid >> 5, L = tid & 31;
    int wm = wid & 1, wn = wid >> 1;
    const float* b2e = b2 + (size_t)e * DM;
    float sw = g_w2max[e] * (1.f / 16256.f);
#pragma unroll
    for (int mi = 0; mi < 4; mi++) {
        int r0 = row0 + wm * 64 + mi * 16 + (L >> 2);
        float sa0 = g_sha[r0] * sw;
        float sa1 = g_sha[r0 + 8] * sw;
        float sc0 = g_aw[r0];
        float sc1 = g_aw[r0 + 8];
#pragma unroll
        for (int nj = 0; nj < 2; nj++) {
            int col = col0 + wn * 16 + nj * 8 + (L & 3) * 2;
            float bb0 = b2e[col], bb1 = b2e[col + 1];
            const int* hh = A.hh[mi][nj];
            const int* xx = A.xx[mi][nj];
            float2 v0, v1;
            v0.x = ((16384.f * hh[0] + 128.f * xx[0]) * sa0 + bb0) * sc0;
            v0.y = ((16384.f * hh[1] + 128.f * xx[1]) * sa0 + bb1) * sc0;
            v1.x = ((16384.f * hh[2] + 128.f * xx[2]) * sa1 + bb0) * sc1;
            v1.y = ((16384.f * hh[3] + 128.f * xx[3]) * sa1 + bb1) * sc1;
            *(float2*)(g_y + (size_t)r0 * DM + col) = v0;
            *(float2*)(g_y + (size_t)(r0 + 8) * DM + col) = v1;
        }
    }
}

// ---------------- combine ----------------
__global__ __launch_bounds__(256) void k_combine(float* __restrict__ out) {
    int t = blockIdx.x;
    int d = threadIdx.x;
    int s0 = g_tokslot[2 * t], s1 = g_tokslot[2 * t + 1];
    const float4* y0 = (const float4*)(g_y + (size_t)s0 * DM);
    const float4* y1 = (const float4*)(g_y + (size_t)s1 * DM);
    float4 a = y0[d], b = y1[d];
    ((float4*)out)[(size_t)t * (DM / 4) + d] =
        make_float4(a.x + b.x, a.y + b.y, a.z + b.z, a.w + b.w);
}

// ---------------- launch ----------------
extern "C" void kernel_launch(void* const* d_in, const int* in_sizes, int n_in,
                              void* d_out, int out_size) {
    const float* x  = (const float*)d_in[0];
    const float* gw = (const float*)d_in[1];
    const float* gb = (const float*)d_in[2];
    const float* w1 = (const float*)d_in[3];
    const float* b1 = (const float*)d_in[4];
    const float* w2 = (const float*)d_in[5];
    const float* b2 = (const float*)d_in[6];
    float* out = (float*)d_out;

    cudaFuncSetAttribute(k_imma1, cudaFuncAttributeMaxDynamicSharedMemorySize, SMEM_BYTES);
    cudaFuncSetAttribute(k_imma2, cudaFuncAttributeMaxDynamicSharedMemorySize, SMEM_BYTES);

    k_init<<<(MAXROWS + 255) / 256, 256>>>();
    k_gate<<<NTOK / 8, 256>>>(x, gw, gb);
    k_off<<<1, 1>>>();
    k_scatter<<<(NTOK + 255) / 256, 256>>>();
    k_xquant<<<MAXROWS, 256>>>(x);
    k_wmax<true><<<dim3(256, NE), 256>>>(w1);
    k_wmax<false><<<dim3(256, NE), 256>>>(w2);
    k_wquant<DM, DF, true><<<dim3(DF / 32, DM / 32, NE), dim3(32, 8)>>>(w1);
    k_wquant<DF, DM, false><<<dim3(DM / 32, DF / 32, NE), dim3(32, 8)>>>(w2);
    k_imma1<<<dim3(DF / BN, MT), 256, SMEM_BYTES>>>(b1);
    k_hquant<<<MAXROWS, 256>>>();
    k_imma2<<<dim3(DM / BN, MT), 256, SMEM_BYTES>>>(b2);
    k_combine<<<NTOK, 256>>>(out);
}

// round 6
// speedup vs baseline: 2.1935x; 2.1935x over previous
#include <cuda_runtime.h>
#include <cuda_fp16.h>
#include <math.h>
#include <stdint.h>

#define NTOK 8192
#define DM 1024
#define DF 4096
#define NE 8
#define BM 128
#define BN 128
#define BK 64
#define MAXROWS (NTOK*2 + NE*BM)   /* 17408 */
#define MT (MAXROWS/BM)            /* 136 */

// smem stage: A-hi 16K, A-lo 16K, B-hi 16K = 48KB; 3 stages
#define AH_OFF 0
#define AL_OFF 16384
#define BH_OFF 32768
#define ST_SIZE 49152
#define SMEM_BYTES (1024 + 3*ST_SIZE)   /* 148480 */

// ---------------- scratch (device globals: allocation-free) ----------------
__device__ __align__(16) __half g_xh[(size_t)MAXROWS * DM];
__device__ __align__(16) __half g_xl[(size_t)MAXROWS * DM];
__device__ __align__(16) __half g_hh[(size_t)MAXROWS * DF];
__device__ __align__(16) __half g_hl[(size_t)MAXROWS * DF];
__device__ __align__(16) __half g_w1h[(size_t)NE * DF * DM];
__device__ __align__(16) __half g_w2h[(size_t)NE * DM * DF];
__device__ __align__(16) float  g_y[(size_t)MAXROWS * DM];
__device__ int   g_atok[MAXROWS];
__device__ float g_aw[MAXROWS];
__device__ int   g_tokslot[NTOK * 2];
__device__ int   g_t2e[NTOK * 2];
__device__ float g_t2w[NTOK * 2];
__device__ int   g_cnt[NE];
__device__ int   g_fill[NE];
__device__ int   g_off[NE + 1];

// ---------------- helpers ----------------
__device__ __forceinline__ uint32_t smem_u32(const void* p) {
    uint32_t a;
    asm("{ .reg .u64 t; cvta.to.shared.u64 t, %1; cvt.u32.u64 %0, t; }" : "=r"(a) : "l"(p));
    return a;
}
#define SWZ(x) ((uint32_t)(x) ^ ((((uint32_t)(x)) >> 3) & 0x70))

__device__ __forceinline__ void cp16(uint32_t dst, const void* src) {
    asm volatile("cp.async.cg.shared.global [%0], [%1], 16;" :: "r"(dst), "l"(src));
}
#define CP_COMMIT() asm volatile("cp.async.commit_group;" ::: "memory")
#define CP_WAIT1()  asm volatile("cp.async.wait_group 1;" ::: "memory")
#define CP_WAIT0()  asm volatile("cp.async.wait_group 0;" ::: "memory")

__device__ __forceinline__ void ldm4(uint32_t* r, uint32_t addr) {
    asm volatile("ldmatrix.sync.aligned.m8n8.x4.shared.b16 {%0,%1,%2,%3}, [%4];"
        : "=r"(r[0]), "=r"(r[1]), "=r"(r[2]), "=r"(r[3]) : "r"(addr));
}
__device__ __forceinline__ void mma16816(float* c, const uint32_t* a, uint32_t b0, uint32_t b1) {
    asm volatile("mma.sync.aligned.m16n8k16.row.col.f32.f16.f16.f32 "
        "{%0,%1,%2,%3}, {%4,%5,%6,%7}, {%8,%9}, {%0,%1,%2,%3};"
        : "+f"(c[0]), "+f"(c[1]), "+f"(c[2]), "+f"(c[3])
        : "r"(a[0]), "r"(a[1]), "r"(a[2]), "r"(a[3]), "r"(b0), "r"(b1));
}

// ---------------- init ----------------
__global__ void k_init() {
    int i = blockIdx.x * blockDim.x + threadIdx.x;
    if (i < MAXROWS) g_atok[i] = -1;
    if (i < NE) { g_cnt[i] = 0; g_fill[i] = 0; }
}

// ---------------- gating ----------------
__global__ __launch_bounds__(256) void k_gate(const float* __restrict__ x,
                                              const float* __restrict__ gw,
                                              const float* __restrict__ gb) {
    __shared__ float sgw[DM * NE];
    int tid = threadIdx.x;
    for (int i = tid; i < DM * NE; i += 256) sgw[i] = gw[i];
    __syncthreads();
    int warp = tid >> 5, lane = tid & 31;
    int t = blockIdx.x * 8 + warp;
    const float* xr = x + (size_t)t * DM;
    float acc[NE];
#pragma unroll
    for (int e = 0; e < NE; e++) acc[e] = 0.f;
    for (int d = lane; d < DM; d += 32) {
        float xv = xr[d];
#pragma unroll
        for (int e = 0; e < NE; e++) acc[e] = fmaf(xv, sgw[d * NE + e], acc[e]);
    }
#pragma unroll
    for (int off = 16; off; off >>= 1)
#pragma unroll
        for (int e = 0; e < NE; e++) acc[e] += __shfl_xor_sync(0xFFFFFFFFu, acc[e], off);
    if (lane == 0) {
        float lg[NE], m = -1e30f;
#pragma unroll
        for (int e = 0; e < NE; e++) { lg[e] = acc[e] + gb[e]; m = fmaxf(m, lg[e]); }
        float ex[NE], s = 0.f;
#pragma unroll
        for (int e = 0; e < NE; e++) { ex[e] = expf(lg[e] - m); s += ex[e]; }
        int e0 = 0;
#pragma unroll
        for (int e = 1; e < NE; e++) if (ex[e] > ex[e0]) e0 = e;
        int e1 = (e0 == 0) ? 1 : 0;
#pragma unroll
        for (int e = 0; e < NE; e++) if (e != e0 && ex[e] > ex[e1]) e1 = e;
        float inv = 1.f / s;
        g_t2e[2 * t] = e0;     g_t2w[2 * t] = ex[e0] * inv;
        g_t2e[2 * t + 1] = e1; g_t2w[2 * t + 1] = ex[e1] * inv;
        atomicAdd(&g_cnt[e0], 1);
        atomicAdd(&g_cnt[e1], 1);
    }
}

__global__ void k_off() {
    g_off[0] = 0;
    for (int e = 0; e < NE; e++)
        g_off[e + 1] = g_off[e] + (((g_cnt[e] + BM - 1) / BM) * BM);
}

__global__ void k_scatter() {
    int t = blockIdx.x * blockDim.x + threadIdx.x;
    if (t >= NTOK) return;
#pragma unroll
    for (int r = 0; r < 2; r++) {
        int e = g_t2e[2 * t + r];
        int p = atomicAdd(&g_fill[e], 1);
        int s = g_off[e] + p;
        g_atok[s] = t;
        g_aw[s] = g_t2w[2 * t + r];
        g_tokslot[2 * t + r] = s;
    }
}

// ---------------- gather + fp16 hi/lo split activations ----------------
__global__ __launch_bounds__(256) void k_actsplit(const float* __restrict__ x) {
    int slot = blockIdx.x;
    int tok = g_atok[slot];
    int t4 = threadIdx.x;
    float4 v = make_float4(0.f, 0.f, 0.f, 0.f);
    if (tok >= 0) v = ((const float4*)(x + (size_t)tok * DM))[t4];
    float vv[4] = {v.x, v.y, v.z, v.w};
    __half h[4], l[4];
#pragma unroll
    for (int i = 0; i < 4; i++) {
        h[i] = __float2half_rn(vv[i]);
        l[i] = __float2half_rn(vv[i] - __half2float(h[i]));
    }
    size_t base = (size_t)slot * DM + t4 * 4;
    __half2 hp0; hp0.x = h[0]; hp0.y = h[1];
    __half2 hp1; hp1.x = h[2]; hp1.y = h[3];
    __half2 lp0; lp0.x = l[0]; lp0.y = l[1];
    __half2 lp1; lp1.x = l[2]; lp1.y = l[3];
    *(__half2*)(g_xh + base)     = hp0;
    *(__half2*)(g_xh + base + 2) = hp1;
    *(__half2*)(g_xl + base)     = lp0;
    *(__half2*)(g_xl + base + 2) = lp1;
}

// ---------------- transpose + fp16 weights (hi limb only) ----------------
// src [e][K][N] (N contiguous) -> dst global [e][N][K] (K contiguous).
// Output referenced as device global INSIDE device code (round-3 lesson).
template <int K, int N, bool IS_W1>
__global__ __launch_bounds__(256) void k_wsplit_t(const float* __restrict__ w) {
    __shared__ float tile[32][33];
    int e = blockIdx.z;
    int n0 = blockIdx.x * 32, k0 = blockIdx.y * 32;
    int tx = threadIdx.x, ty = threadIdx.y;
    const float* we = w + (size_t)e * K * N;
    for (int i = ty; i < 32; i += 8)
        tile[i][tx] = we[(size_t)(k0 + i) * N + n0 + tx];
    __syncthreads();
    __half* ohe = (IS_W1 ? g_w1h : g_w2h) + (size_t)e * N * K;
    for (int i = ty; i < 32; i += 8)
        ohe[(size_t)(n0 + i) * K + k0 + tx] = __float2half_rn(tile[tx][i]);
}

// ================= HMMA mainloop: (ah + al) x bh, 2 passes =================
struct Acc { float v[4][4][4]; };   // [mi][ni][frag]

__device__ __forceinline__ void hmma_mainloop(
    uint32_t sb, Acc& A,
    const __half* Ah, const __half* Al, int astride,
    const __half* Bh, int bstride,
    int NC, int tid)
{
    int wid = tid >> 5, L = tid & 31;
    int wm = wid & 1, wn = wid >> 1;   // 2 x 4 warp grid, warp tile 64x32

    int fr = tid & 127;                // fill row
    int hb = (tid >> 7) * 64;          // byte half within 128B row

    auto fill = [&](int s, int c) {
        uint32_t st = sb + s * ST_SIZE;
        const char* pah = (const char*)(Ah + (size_t)fr * astride + c * BK) + hb;
        const char* pal = (const char*)(Al + (size_t)fr * astride + c * BK) + hb;
        const char* pbh = (const char*)(Bh + (size_t)fr * bstride + c * BK) + hb;
        uint32_t rb = fr * 128 + hb;
#pragma unroll
        for (int j = 0; j < 4; j++) {
            uint32_t o = SWZ(rb + j * 16);
            cp16(st + AH_OFF + o, pah + j * 16);
            cp16(st + AL_OFF + o, pal + j * 16);
            cp16(st + BH_OFF + o, pbh + j * 16);
        }
    };

    fill(0, 0); CP_COMMIT();
    fill(1, 1); CP_COMMIT();

    int lrow = L & 15;
    int lkb = (L >> 4) * 16;

    for (int c = 0; c < NC; c++) {
        if (c + 1 < NC) CP_WAIT1(); else CP_WAIT0();
        __syncthreads();
        if (c + 2 < NC) { fill((c + 2) % 3, c + 2); CP_COMMIT(); }
        uint32_t st = sb + (c % 3) * ST_SIZE;

#pragma unroll
        for (int ks = 0; ks < 4; ks++) {
            uint32_t kb = ks * 32 + lkb;
            uint32_t ah[4][4], al[4][4], bh[2][4];
#pragma unroll
            for (int mi = 0; mi < 4; mi++) {
                uint32_t ro = (wm * 64 + mi * 16 + lrow) * 128 + kb;
                ldm4(ah[mi], st + AH_OFF + SWZ(ro));
                ldm4(al[mi], st + AL_OFF + SWZ(ro));
            }
#pragma unroll
            for (int nj = 0; nj < 2; nj++) {
                uint32_t ro = (wn * 32 + nj * 16 + lrow) * 128 + kb;
                ldm4(bh[nj], st + BH_OFF + SWZ(ro));
            }
#pragma unroll
            for (int mi = 0; mi < 4; mi++)
#pragma unroll
                for (int ni = 0; ni < 4; ni++) {
                    int nj = ni >> 1, hf = ni & 1;
                    float* acc = A.v[mi][ni];
                    mma16816(acc, ah[mi], bh[nj][hf], bh[nj][hf + 2]);
                    mma16816(acc, al[mi], bh[nj][hf], bh[nj][hf + 2]);
                }
        }
    }
}

// ---------------- GEMM1: h = relu(x @ w1 + b1), split to fp16 hi/lo ----------------
__global__ __launch_bounds__(256, 1) void k_fmma1(const float* __restrict__ b1) {
    extern __shared__ char smem[];
    int row0 = blockIdx.y * BM;
    if (row0 >= g_off[NE]) return;
    int e = 0;
#pragma unroll
    for (int i = 0; i < NE - 1; i++) if (g_off[i + 1] <= row0) e = i + 1;
    int col0 = blockIdx.x * BN;
    uint32_t sb = (smem_u32(smem) + 1023) & ~1023u;
    int tid = threadIdx.x;

    Acc A;
#pragma unroll
    for (int i = 0; i < 4; i++)
#pragma unroll
        for (int j = 0; j < 4; j++)
#pragma unroll
            for (int k = 0; k < 4; k++) A.v[i][j][k] = 0.f;

    hmma_mainloop(sb, A,
                  g_xh + (size_t)row0 * DM, g_xl + (size_t)row0 * DM, DM,
                  g_w1h + (size_t)e * DF * DM + (size_t)col0 * DM, DM,
                  DM / BK, tid);

    int wid = tid >> 5, L = tid & 31;
    int wm = wid & 1, wn = wid >> 1;
    const float* b1e = b1 + (size_t)e * DF;
#pragma unroll
    for (int mi = 0; mi < 4; mi++) {
        int r0 = row0 + wm * 64 + mi * 16 + (L >> 2);
#pragma unroll
        for (int ni = 0; ni < 4; ni++) {
            int col = col0 + wn * 32 + ni * 8 + (L & 3) * 2;
            float bb0 = b1e[col], bb1 = b1e[col + 1];
            float* a = A.v[mi][ni];
#pragma unroll
            for (int hrow = 0; hrow < 2; hrow++) {
                int row = r0 + hrow * 8;
                float v0 = fmaxf(a[hrow * 2 + 0] + bb0, 0.f);
                float v1 = fmaxf(a[hrow * 2 + 1] + bb1, 0.f);
                __half h0 = __float2half_rn(v0);
                __half h1 = __float2half_rn(v1);
                __half2 hp; hp.x = h0; hp.y = h1;
                __half2 lp;
                lp.x = __float2half_rn(v0 - __half2float(h0));
                lp.y = __float2half_rn(v1 - __half2float(h1));
                size_t o = (size_t)row * DF + col;
                *(__half2*)(g_hh + o) = hp;
                *(__half2*)(g_hl + o) = lp;
            }
        }
    }
}

// ---------------- GEMM2: y = (h @ w2 + b2) * gate ----------------
__global__ __launch_bounds__(256, 1) void k_fmma2(const float* __restrict__ b2) {
    extern __shared__ char smem[];
    int row0 = blockIdx.y * BM;
    if (row0 >= g_off[NE]) return;
    int e = 0;
#pragma unroll
    for (int i = 0; i < NE - 1; i++) if (g_off[i + 1] <= row0) e = i + 1;
    int col0 = blockIdx.x * BN;
    uint32_t sb = (smem_u32(smem) + 1023) & ~1023u;
    int tid = threadIdx.x;

    Acc A;
#pragma unroll
    for (int i = 0; i < 4; i++)
#pragma unroll
        for (int j = 0; j < 4; j++)
#pragma unroll
            for (int k = 0; k < 4; k++) A.v[i][j][k] = 0.f;

    hmma_mainloop(sb, A,
                  g_hh + (size_t)row0 * DF, g_hl + (size_t)row0 * DF, DF,
                  g_w2h + (size_t)e * DM * DF + (size_t)col0 * DF, DF,
                  DF / BK, tid);

    int wid = tid >> 5, L = tid & 31;
    int wm = wid & 1, wn = wid >> 1;
    const float* b2e = b2 + (size_t)e * DM;
#pragma unroll
    for (int mi = 0; mi < 4; mi++) {
        int r0 = row0 + wm * 64 + mi * 16 + (L >> 2);
#pragma unroll
        for (int ni = 0; ni < 4; ni++) {
            int col = col0 + wn * 32 + ni * 8 + (L & 3) * 2;
            float bb0 = b2e[col], bb1 = b2e[col + 1];
            float* a = A.v[mi][ni];
#pragma unroll
            for (int hrow = 0; hrow < 2; hrow++) {
                int row = r0 + hrow * 8;
                float sc = g_aw[row];
                float2 v;
                v.x = (a[hrow * 2 + 0] + bb0) * sc;
                v.y = (a[hrow * 2 + 1] + bb1) * sc;
                *(float2*)(g_y + (size_t)row * DM + col) = v;
            }
        }
    }
}

// ---------------- combine ----------------
__global__ __launch_bounds__(256) void k_combine(float* __restrict__ out) {
    int t = blockIdx.x;
    int d = threadIdx.x;
    int s0 = g_tokslot[2 * t], s1 = g_tokslot[2 * t + 1];
    const float4* y0 = (const float4*)(g_y + (size_t)s0 * DM);
    const float4* y1 = (const float4*)(g_y + (size_t)s1 * DM);
    float4 a = y0[d], b = y1[d];
    ((float4*)out)[(size_t)t * (DM / 4) + d] =
        make_float4(a.x + b.x, a.y + b.y, a.z + b.z, a.w + b.w);
}

// ---------------- launch ----------------
extern "C" void kernel_launch(void* const* d_in, const int* in_sizes, int n_in,
                              void* d_out, int out_size) {
    const float* x  = (const float*)d_in[0];
    const float* gw = (const float*)d_in[1];
    const float* gb = (const float*)d_in[2];
    const float* w1 = (const float*)d_in[3];
    const float* b1 = (const float*)d_in[4];
    const float* w2 = (const float*)d_in[5];
    const float* b2 = (const float*)d_in[6];
    float* out = (float*)d_out;

    cudaFuncSetAttribute(k_fmma1, cudaFuncAttributeMaxDynamicSharedMemorySize, SMEM_BYTES);
    cudaFuncSetAttribute(k_fmma2, cudaFuncAttributeMaxDynamicSharedMemorySize, SMEM_BYTES);

    k_init<<<(MAXROWS + 255) / 256, 256>>>();
    k_gate<<<NTOK / 8, 256>>>(x, gw, gb);
    k_off<<<1, 1>>>();
    k_scatter<<<(NTOK + 255) / 256, 256>>>();
    k_actsplit<<<MAXROWS, 256>>>(x);
    k_wsplit_t<DM, DF, true><<<dim3(DF / 32, DM / 32, NE), dim3(32, 8)>>>(w1);
    k_wsplit_t<DF, DM, false><<<dim3(DM / 32, DF / 32, NE), dim3(32, 8)>>>(w2);
    k_fmma1<<<dim3(DF / BN, MT), 256, SMEM_BYTES>>>(b1);
    k_fmma2<<<dim3(DM / BN, MT), 256, SMEM_BYTES>>>(b2);
    k_combine<<<NTOK, 256>>>(out);
}

// round 7
// speedup vs baseline: 2.3830x; 1.0864x over previous
#include <cuda_runtime.h>
#include <cuda_fp16.h>
#include <math.h>
#include <stdint.h>

#define NTOK 8192
#define DM 1024
#define DF 4096
#define NE 8
#define BM 128
#define BN 128
#define BK 64
#define MAXROWS (NTOK*2 + NE*BM)   /* 17408 */
#define MT (MAXROWS/BM)            /* 136 */

// smem stage: A 16K + B 16K = 32KB; 4 stages
#define A_OFF 0
#define B_OFF 16384
#define ST_SIZE 32768
#define NSTAGE 4
#define SMEM_BYTES (1024 + NSTAGE*ST_SIZE)   /* 132096 */

// ---------------- scratch (device globals: allocation-free) ----------------
__device__ __align__(16) __half g_xq[(size_t)MAXROWS * DM];
__device__ __align__(16) __half g_hq[(size_t)MAXROWS * DF];
__device__ __align__(16) __half g_w1h[(size_t)NE * DF * DM];
__device__ __align__(16) __half g_w2h[(size_t)NE * DM * DF];
__device__ __align__(16) float  g_y[(size_t)MAXROWS * DM];
__device__ int   g_atok[MAXROWS];
__device__ float g_aw[MAXROWS];
__device__ int   g_tokslot[NTOK * 2];
__device__ int   g_t2e[NTOK * 2];
__device__ float g_t2w[NTOK * 2];
__device__ int   g_cnt[NE];
__device__ int   g_fill[NE];
__device__ int   g_off[NE + 1];

// ---------------- helpers ----------------
__device__ __forceinline__ uint32_t smem_u32(const void* p) {
    uint32_t a;
    asm("{ .reg .u64 t; cvta.to.shared.u64 t, %1; cvt.u32.u64 %0, t; }" : "=r"(a) : "l"(p));
    return a;
}
#define SWZ(x) ((uint32_t)(x) ^ ((((uint32_t)(x)) >> 3) & 0x70))

__device__ __forceinline__ void cp16(uint32_t dst, const void* src) {
    asm volatile("cp.async.cg.shared.global [%0], [%1], 16;" :: "r"(dst), "l"(src));
}
#define CP_COMMIT() asm volatile("cp.async.commit_group;" ::: "memory")
#define CP_WAITN()  asm volatile("cp.async.wait_group %0;" :: "n"(NSTAGE - 2) : "memory")
#define CP_WAIT0()  asm volatile("cp.async.wait_group 0;" ::: "memory")

__device__ __forceinline__ void ldm4(uint32_t* r, uint32_t addr) {
    asm volatile("ldmatrix.sync.aligned.m8n8.x4.shared.b16 {%0,%1,%2,%3}, [%4];"
        : "=r"(r[0]), "=r"(r[1]), "=r"(r[2]), "=r"(r[3]) : "r"(addr));
}
__device__ __forceinline__ void mma16816(float* c, const uint32_t* a, uint32_t b0, uint32_t b1) {
    asm volatile("mma.sync.aligned.m16n8k16.row.col.f32.f16.f16.f32 "
        "{%0,%1,%2,%3}, {%4,%5,%6,%7}, {%8,%9}, {%0,%1,%2,%3};"
        : "+f"(c[0]), "+f"(c[1]), "+f"(c[2]), "+f"(c[3])
        : "r"(a[0]), "r"(a[1]), "r"(a[2]), "r"(a[3]), "r"(b0), "r"(b1));
}

// ---------------- init ----------------
__global__ void k_init() {
    int i = blockIdx.x * blockDim.x + threadIdx.x;
    if (i < MAXROWS) g_atok[i] = -1;
    if (i < NE) { g_cnt[i] = 0; g_fill[i] = 0; }
}

// ---------------- gating ----------------
__global__ __launch_bounds__(256) void k_gate(const float* __restrict__ x,
                                              const float* __restrict__ gw,
                                              const float* __restrict__ gb) {
    __shared__ float sgw[DM * NE];
    int tid = threadIdx.x;
    for (int i = tid; i < DM * NE; i += 256) sgw[i] = gw[i];
    __syncthreads();
    int warp = tid >> 5, lane = tid & 31;
    int t = blockIdx.x * 8 + warp;
    const float* xr = x + (size_t)t * DM;
    float acc[NE];
#pragma unroll
    for (int e = 0; e < NE; e++) acc[e] = 0.f;
    for (int d = lane; d < DM; d += 32) {
        float xv = xr[d];
#pragma unroll
        for (int e = 0; e < NE; e++) acc[e] = fmaf(xv, sgw[d * NE + e], acc[e]);
    }
#pragma unroll
    for (int off = 16; off; off >>= 1)
#pragma unroll
        for (int e = 0; e < NE; e++) acc[e] += __shfl_xor_sync(0xFFFFFFFFu, acc[e], off);
    if (lane == 0) {
        float lg[NE], m = -1e30f;
#pragma unroll
        for (int e = 0; e < NE; e++) { lg[e] = acc[e] + gb[e]; m = fmaxf(m, lg[e]); }
        float ex[NE], s = 0.f;
#pragma unroll
        for (int e = 0; e < NE; e++) { ex[e] = expf(lg[e] - m); s += ex[e]; }
        int e0 = 0;
#pragma unroll
        for (int e = 1; e < NE; e++) if (ex[e] > ex[e0]) e0 = e;
        int e1 = (e0 == 0) ? 1 : 0;
#pragma unroll
        for (int e = 0; e < NE; e++) if (e != e0 && ex[e] > ex[e1]) e1 = e;
        float inv = 1.f / s;
        g_t2e[2 * t] = e0;     g_t2w[2 * t] = ex[e0] * inv;
        g_t2e[2 * t + 1] = e1; g_t2w[2 * t + 1] = ex[e1] * inv;
        atomicAdd(&g_cnt[e0], 1);
        atomicAdd(&g_cnt[e1], 1);
    }
}

__global__ void k_off() {
    g_off[0] = 0;
    for (int e = 0; e < NE; e++)
        g_off[e + 1] = g_off[e] + (((g_cnt[e] + BM - 1) / BM) * BM);
}

__global__ void k_scatter() {
    int t = blockIdx.x * blockDim.x + threadIdx.x;
    if (t >= NTOK) return;
#pragma unroll
    for (int r = 0; r < 2; r++) {
        int e = g_t2e[2 * t + r];
        int p = atomicAdd(&g_fill[e], 1);
        int s = g_off[e] + p;
        g_atok[s] = t;
        g_aw[s] = g_t2w[2 * t + r];
        g_tokslot[2 * t + r] = s;
    }
}

// ---------------- gather + fp16 activations ----------------
__global__ __launch_bounds__(256) void k_actsplit(const float* __restrict__ x) {
    int slot = blockIdx.x;
    int tok = g_atok[slot];
    int t4 = threadIdx.x;
    float4 v = make_float4(0.f, 0.f, 0.f, 0.f);
    if (tok >= 0) v = ((const float4*)(x + (size_t)tok * DM))[t4];
    __half2 p0; p0.x = __float2half_rn(v.x); p0.y = __float2half_rn(v.y);
    __half2 p1; p1.x = __float2half_rn(v.z); p1.y = __float2half_rn(v.w);
    size_t base = (size_t)slot * DM + t4 * 4;
    *(__half2*)(g_xq + base)     = p0;
    *(__half2*)(g_xq + base + 2) = p1;
}

// ---------------- transpose + fp16 weights ----------------
// src [e][K][N] (N contiguous) -> dst global [e][N][K] (K contiguous).
// Output referenced as device global INSIDE device code (round-3 lesson).
template <int K, int N, bool IS_W1>
__global__ __launch_bounds__(256) void k_wsplit_t(const float* __restrict__ w) {
    __shared__ float tile[32][33];
    int e = blockIdx.z;
    int n0 = blockIdx.x * 32, k0 = blockIdx.y * 32;
    int tx = threadIdx.x, ty = threadIdx.y;
    const float* we = w + (size_t)e * K * N;
    for (int i = ty; i < 32; i += 8)
        tile[i][tx] = we[(size_t)(k0 + i) * N + n0 + tx];
    __syncthreads();
    __half* ohe = (IS_W1 ? g_w1h : g_w2h) + (size_t)e * N * K;
    for (int i = ty; i < 32; i += 8)
        ohe[(size_t)(n0 + i) * K + k0 + tx] = __float2half_rn(tile[tx][i]);
}

// ================= HMMA mainloop: single fp16 pass, 4-stage pipeline =================
struct Acc { float v[4][4][4]; };   // [mi][ni][frag]

__device__ __forceinline__ void hmma_mainloop(
    uint32_t sb, Acc& A,
    const __half* Ap, int astride,
    const __half* Bp, int bstride,
    int NC, int tid)
{
    int wid = tid >> 5, L = tid & 31;
    int wm = wid & 1, wn = wid >> 1;   // 2 x 4 warp grid, warp tile 64x32

    int fr = tid & 127;                // fill row
    int hb = (tid >> 7) * 64;          // byte half within 128B row

    auto fill = [&](int s, int c) {
        uint32_t st = sb + s * ST_SIZE;
        const char* pa = (const char*)(Ap + (size_t)fr * astride + c * BK) + hb;
        const char* pb = (const char*)(Bp + (size_t)fr * bstride + c * BK) + hb;
        uint32_t rb = fr * 128 + hb;
#pragma unroll
        for (int j = 0; j < 4; j++) {
            uint32_t o = SWZ(rb + j * 16);
            cp16(st + A_OFF + o, pa + j * 16);
            cp16(st + B_OFF + o, pb + j * 16);
        }
    };

#pragma unroll
    for (int p = 0; p < NSTAGE - 1; p++) { fill(p, p); CP_COMMIT(); }

    int lrow = L & 15;
    int lkb = (L >> 4) * 16;

    for (int c = 0; c < NC; c++) {
        if (c + NSTAGE - 1 < NC) CP_WAITN(); else CP_WAIT0();
        __syncthreads();
        if (c + NSTAGE - 1 < NC) { fill((c + NSTAGE - 1) % NSTAGE, c + NSTAGE - 1); CP_COMMIT(); }
        uint32_t st = sb + (c % NSTAGE) * ST_SIZE;

#pragma unroll
        for (int ks = 0; ks < 4; ks++) {
            uint32_t kb = ks * 32 + lkb;
            uint32_t ah[4][4], bh[2][4];
#pragma unroll
            for (int mi = 0; mi < 4; mi++) {
                uint32_t ro = (wm * 64 + mi * 16 + lrow) * 128 + kb;
                ldm4(ah[mi], st + A_OFF + SWZ(ro));
            }
#pragma unroll
            for (int nj = 0; nj < 2; nj++) {
                uint32_t ro = (wn * 32 + nj * 16 + lrow) * 128 + kb;
                ldm4(bh[nj], st + B_OFF + SWZ(ro));
            }
#pragma unroll
            for (int mi = 0; mi < 4; mi++)
#pragma unroll
                for (int ni = 0; ni < 4; ni++) {
                    int nj = ni >> 1, hf = ni & 1;
                    mma16816(A.v[mi][ni], ah[mi], bh[nj][hf], bh[nj][hf + 2]);
                }
        }
    }
}

// ---------------- GEMM1: h = relu(x @ w1 + b1) -> fp16 ----------------
__global__ __launch_bounds__(256, 1) void k_fmma1(const float* __restrict__ b1) {
    extern __shared__ char smem[];
    int row0 = blockIdx.y * BM;
    if (row0 >= g_off[NE]) return;
    int e = 0;
#pragma unroll
    for (int i = 0; i < NE - 1; i++) if (g_off[i + 1] <= row0) e = i + 1;
    int col0 = blockIdx.x * BN;
    uint32_t sb = (smem_u32(smem) + 1023) & ~1023u;
    int tid = threadIdx.x;

    Acc A;
#pragma unroll
    for (int i = 0; i < 4; i++)
#pragma unroll
        for (int j = 0; j < 4; j++)
#pragma unroll
            for (int k = 0; k < 4; k++) A.v[i][j][k] = 0.f;

    hmma_mainloop(sb, A,
                  g_xq + (size_t)row0 * DM, DM,
                  g_w1h + (size_t)e * DF * DM + (size_t)col0 * DM, DM,
                  DM / BK, tid);

    int wid = tid >> 5, L = tid & 31;
    int wm = wid & 1, wn = wid >> 1;
    const float* b1e = b1 + (size_t)e * DF;
#pragma unroll
    for (int mi = 0; mi < 4; mi++) {
        int r0 = row0 + wm * 64 + mi * 16 + (L >> 2);
#pragma unroll
        for (int ni = 0; ni < 4; ni++) {
            int col = col0 + wn * 32 + ni * 8 + (L & 3) * 2;
            float bb0 = b1e[col], bb1 = b1e[col + 1];
            float* a = A.v[mi][ni];
#pragma unroll
            for (int hrow = 0; hrow < 2; hrow++) {
                int row = r0 + hrow * 8;
                __half2 hp;
                hp.x = __float2half_rn(fmaxf(a[hrow * 2 + 0] + bb0, 0.f));
                hp.y = __float2half_rn(fmaxf(a[hrow * 2 + 1] + bb1, 0.f));
                *(__half2*)(g_hq + (size_t)row * DF + col) = hp;
            }
        }
    }
}

// ---------------- GEMM2: y = (h @ w2 + b2) * gate ----------------
__global__ __launch_bounds__(256, 1) void k_fmma2(const float* __restrict__ b2) {
    extern __shared__ char smem[];
    int row0 = blockIdx.y * BM;
    if (row0 >= g_off[NE]) return;
    int e = 0;
#pragma unroll
    for (int i = 0; i < NE - 1; i++) if (g_off[i + 1] <= row0) e = i + 1;
    int col0 = blockIdx.x * BN;
    uint32_t sb = (smem_u32(smem) + 1023) & ~1023u;
    int tid = threadIdx.x;

    Acc A;
#pragma unroll
    for (int i = 0; i < 4; i++)
#pragma unroll
        for (int j = 0; j < 4; j++)
#pragma unroll
            for (int k = 0; k < 4; k++) A.v[i][j][k] = 0.f;

    hmma_mainloop(sb, A,
                  g_hq + (size_t)row0 * DF, DF,
                  g_w2h + (size_t)e * DM * DF + (size_t)col0 * DF, DF,
                  DF / BK, tid);

    int wid = tid >> 5, L = tid & 31;
    int wm = wid & 1, wn = wid >> 1;
    const float* b2e = b2 + (size_t)e * DM;
#pragma unroll
    for (int mi = 0; mi < 4; mi++) {
        int r0 = row0 + wm * 64 + mi * 16 + (L >> 2);
#pragma unroll
        for (int ni = 0; ni < 4; ni++) {
            int col = col0 + wn * 32 + ni * 8 + (L & 3) * 2;
            float bb0 = b2e[col], bb1 = b2e[col + 1];
            float* a = A.v[mi][ni];
#pragma unroll
            for (int hrow = 0; hrow < 2; hrow++) {
                int row = r0 + hrow * 8;
                float sc = g_aw[row];
                float2 v;
                v.x = (a[hrow * 2 + 0] + bb0) * sc;
                v.y = (a[hrow * 2 + 1] + bb1) * sc;
                *(float2*)(g_y + (size_t)row * DM + col) = v;
            }
        }
    }
}

// ---------------- combine ----------------
__global__ __launch_bounds__(256) void k_combine(float* __restrict__ out) {
    int t = blockIdx.x;
    int d = threadIdx.x;
    int s0 = g_tokslot[2 * t], s1 = g_tokslot[2 * t + 1];
    const float4* y0 = (const float4*)(g_y + (size_t)s0 * DM);
    const float4* y1 = (const float4*)(g_y + (size_t)s1 * DM);
    float4 a = y0[d], b = y1[d];
    ((float4*)out)[(size_t)t * (DM / 4) + d] =
        make_float4(a.x + b.x, a.y + b.y, a.z + b.z, a.w + b.w);
}

// ---------------- launch ----------------
extern "C" void kernel_launch(void* const* d_in, const int* in_sizes, int n_in,
                              void* d_out, int out_size) {
    const float* x  = (const float*)d_in[0];
    const float* gw = (const float*)d_in[1];
    const float* gb = (const float*)d_in[2];
    const float* w1 = (const float*)d_in[3];
    const float* b1 = (const float*)d_in[4];
    const float* w2 = (const float*)d_in[5];
    const float* b2 = (const float*)d_in[6];
    float* out = (float*)d_out;

    cudaFuncSetAttribute(k_fmma1, cudaFuncAttributeMaxDynamicSharedMemorySize, SMEM_BYTES);
    cudaFuncSetAttribute(k_fmma2, cudaFuncAttributeMaxDynamicSharedMemorySize, SMEM_BYTES);

    k_init<<<(MAXROWS + 255) / 256, 256>>>();
    k_gate<<<NTOK / 8, 256>>>(x, gw, gb);
    k_off<<<1, 1>>>();
    k_scatter<<<(NTOK + 255) / 256, 256>>>();
    k_actsplit<<<MAXROWS, 256>>>(x);
    k_wsplit_t<DM, DF, true><<<dim3(DF / 32, DM / 32, NE), dim3(32, 8)>>>(w1);
    k_wsplit_t<DF, DM, false><<<dim3(DM / 32, DF / 32, NE), dim3(32, 8)>>>(w2);
    k_fmma1<<<dim3(DF / BN, MT), 256, SMEM_BYTES>>>(b1);
    k_fmma2<<<dim3(DM / BN, MT), 256, SMEM_BYTES>>>(b2);
    k_combine<<<NTOK, 256>>>(out);
}

// round 9
// speedup vs baseline: 3.9084x; 1.6401x over previous
#include <cuda_runtime.h>
#include <cuda_fp16.h>
#include <math.h>
#include <stdint.h>

#define NTOK 8192
#define DM 1024
#define DF 4096
#define NE 8
#define BM 128
#define BN 128
#define BK 64
#define MAXROWS (NTOK*2 + NE*BM)   /* 17408 */
#define MT (MAXROWS/BM)            /* 136 */

// smem stage: A 16K + B 16K = 32KB; 3 stages -> 99KB total -> 2 CTAs/SM
#define A_OFF 0
#define B_OFF 16384
#define ST_SIZE 32768
#define NSTAGE 3
#define SMEM_BYTES (1024 + NSTAGE*ST_SIZE)   /* 99328 */

// ---------------- scratch (device globals: allocation-free) ----------------
__device__ __align__(16) __half g_xq[(size_t)MAXROWS * DM];
__device__ __align__(16) __half g_hq[(size_t)MAXROWS * DF];
__device__ __align__(16) __half g_w1h[(size_t)NE * DF * DM];
__device__ __align__(16) __half g_w2h[(size_t)NE * DM * DF];
__device__ int   g_atok[MAXROWS];
__device__ float g_aw[MAXROWS];
__device__ int   g_t2e[NTOK * 2];
__device__ float g_t2w[NTOK * 2];
__device__ int   g_cnt[NE];
__device__ int   g_fill[NE];
__device__ int   g_off[NE + 1];

// ---------------- helpers ----------------
__device__ __forceinline__ uint32_t smem_u32(const void* p) {
    uint32_t a;
    asm("{ .reg .u64 t; cvta.to.shared.u64 t, %1; cvt.u32.u64 %0, t; }" : "=r"(a) : "l"(p));
    return a;
}
#define SWZ(x) ((uint32_t)(x) ^ ((((uint32_t)(x)) >> 3) & 0x70))

__device__ __forceinline__ void cp16(uint32_t dst, const void* src) {
    asm volatile("cp.async.cg.shared.global [%0], [%1], 16;" :: "r"(dst), "l"(src));
}
#define CP_COMMIT() asm volatile("cp.async.commit_group;" ::: "memory")
#define CP_WAITN()  asm volatile("cp.async.wait_group %0;" :: "n"(NSTAGE - 2) : "memory")
#define CP_WAIT0()  asm volatile("cp.async.wait_group 0;" ::: "memory")

__device__ __forceinline__ void ldm4(uint32_t* r, uint32_t addr) {
    asm volatile("ldmatrix.sync.aligned.m8n8.x4.shared.b16 {%0,%1,%2,%3}, [%4];"
        : "=r"(r[0]), "=r"(r[1]), "=r"(r[2]), "=r"(r[3]) : "r"(addr));
}
__device__ __forceinline__ void mma16816(float* c, const uint32_t* a, uint32_t b0, uint32_t b1) {
    asm volatile("mma.sync.aligned.m16n8k16.row.col.f32.f16.f16.f32 "
        "{%0,%1,%2,%3}, {%4,%5,%6,%7}, {%8,%9}, {%0,%1,%2,%3};"
        : "+f"(c[0]), "+f"(c[1]), "+f"(c[2]), "+f"(c[3])
        : "r"(a[0]), "r"(a[1]), "r"(a[2]), "r"(a[3]), "r"(b0), "r"(b1));
}

// ---------------- init ----------------
__global__ void k_init() {
    int i = blockIdx.x * blockDim.x + threadIdx.x;
    if (i < MAXROWS) g_atok[i] = -1;
    if (i < NE) { g_cnt[i] = 0; g_fill[i] = 0; }
}

__global__ void k_zero(float* __restrict__ out) {
    ((float4*)out)[blockIdx.x * 256 + threadIdx.x] = make_float4(0.f, 0.f, 0.f, 0.f);
}

// ---------------- gating ----------------
__global__ __launch_bounds__(256) void k_gate(const float* __restrict__ x,
                                              const float* __restrict__ gw,
                                              const float* __restrict__ gb) {
    __shared__ float sgw[DM * NE];
    int tid = threadIdx.x;
    for (int i = tid; i < DM * NE; i += 256) sgw[i] = gw[i];
    __syncthreads();
    int warp = tid >> 5, lane = tid & 31;
    int t = blockIdx.x * 8 + warp;
    const float* xr = x + (size_t)t * DM;
    float acc[NE];
#pragma unroll
    for (int e = 0; e < NE; e++) acc[e] = 0.f;
    for (int d = lane; d < DM; d += 32) {
        float xv = xr[d];
#pragma unroll
        for (int e = 0; e < NE; e++) acc[e] = fmaf(xv, sgw[d * NE + e], acc[e]);
    }
#pragma unroll
    for (int off = 16; off; off >>= 1)
#pragma unroll
        for (int e = 0; e < NE; e++) acc[e] += __shfl_xor_sync(0xFFFFFFFFu, acc[e], off);
    if (lane == 0) {
        float lg[NE], m = -1e30f;
#pragma unroll
        for (int e = 0; e < NE; e++) { lg[e] = acc[e] + gb[e]; m = fmaxf(m, lg[e]); }
        float ex[NE], s = 0.f;
#pragma unroll
        for (int e = 0; e < NE; e++) { ex[e] = expf(lg[e] - m); s += ex[e]; }
        int e0 = 0;
#pragma unroll
        for (int e = 1; e < NE; e++) if (ex[e] > ex[e0]) e0 = e;
        int e1 = (e0 == 0) ? 1 : 0;
#pragma unroll
        for (int e = 0; e < NE; e++) if (e != e0 && ex[e] > ex[e1]) e1 = e;
        float inv = 1.f / s;
        g_t2e[2 * t] = e0;     g_t2w[2 * t] = ex[e0] * inv;
        g_t2e[2 * t + 1] = e1; g_t2w[2 * t + 1] = ex[e1] * inv;
        atomicAdd(&g_cnt[e0], 1);
        atomicAdd(&g_cnt[e1], 1);
    }
}

__global__ void k_off() {
    g_off[0] = 0;
    for (int e = 0; e < NE; e++)
        g_off[e + 1] = g_off[e] + (((g_cnt[e] + BM - 1) / BM) * BM);
}

__global__ void k_scatter() {
    int t = blockIdx.x * blockDim.x + threadIdx.x;
    if (t >= NTOK) return;
#pragma unroll
    for (int r = 0; r < 2; r++) {
        int e = g_t2e[2 * t + r];
        int p = atomicAdd(&g_fill[e], 1);
        int s = g_off[e] + p;
        g_atok[s] = t;
        g_aw[s] = g_t2w[2 * t + r];
    }
}

// ---------------- gather + fp16 activations ----------------
__global__ __launch_bounds__(256) void k_actsplit(const float* __restrict__ x) {
    int slot = blockIdx.x;
    int tok = g_atok[slot];
    int t4 = threadIdx.x;
    float4 v = make_float4(0.f, 0.f, 0.f, 0.f);
    if (tok >= 0) v = ((const float4*)(x + (size_t)tok * DM))[t4];
    __half2 p0; p0.x = __float2half_rn(v.x); p0.y = __float2half_rn(v.y);
    __half2 p1; p1.x = __float2half_rn(v.z); p1.y = __float2half_rn(v.w);
    size_t base = (size_t)slot * DM + t4 * 4;
    *(__half2*)(g_xq + base)     = p0;
    *(__half2*)(g_xq + base + 2) = p1;
}

// ---------------- transpose + fp16 weights ----------------
// src [e][K][N] (N contiguous) -> dst global [e][N][K] (K contiguous).
// Output referenced as device global INSIDE device code (round-3 lesson).
template <int K, int N, bool IS_W1>
__global__ __launch_bounds__(256) void k_wsplit_t(const float* __restrict__ w) {
    __shared__ float tile[32][33];
    int e = blockIdx.z;
    int n0 = blockIdx.x * 32, k0 = blockIdx.y * 32;
    int tx = threadIdx.x, ty = threadIdx.y;
    const float* we = w + (size_t)e * K * N;
    for (int i = ty; i < 32; i += 8)
        tile[i][tx] = we[(size_t)(k0 + i) * N + n0 + tx];
    __syncthreads();
    __half* ohe = (IS_W1 ? g_w1h : g_w2h) + (size_t)e * N * K;
    for (int i = ty; i < 32; i += 8)
        ohe[(size_t)(n0 + i) * K + k0 + tx] = __float2half_rn(tile[tx][i]);
}

// ================= HMMA mainloop: single fp16 pass, 3-stage, 2 CTAs/SM =================
struct Acc { float v[4][4][4]; };   // [mi][ni][frag]

__device__ __forceinline__ void hmma_mainloop(
    uint32_t sb, Acc& A,
    const __half* Ap, int astride,
    const __half* Bp, int bstride,
    int NC, int tid)
{
    int wid = tid >> 5, L = tid & 31;
    int wm = wid & 1, wn = wid >> 1;   // 2 x 4 warp grid, warp tile 64x32

    int fr = tid & 127;                // fill row
    int hb = (tid >> 7) * 64;          // byte half within 128B row

    auto fill = [&](int s, int c) {
        uint32_t st = sb + s * ST_SIZE;
        const char* pa = (const char*)(Ap + (size_t)fr * astride + c * BK) + hb;
        const char* pb = (const char*)(Bp + (size_t)fr * bstride + c * BK) + hb;
        uint32_t rb = fr * 128 + hb;
#pragma unroll
        for (int j = 0; j < 4; j++) {
            uint32_t o = SWZ(rb + j * 16);
            cp16(st + A_OFF + o, pa + j * 16);
            cp16(st + B_OFF + o, pb + j * 16);
        }
    };

#pragma unroll
    for (int p = 0; p < NSTAGE - 1; p++) { fill(p, p); CP_COMMIT(); }

    int lrow = L & 15;
    int lkb = (L >> 4) * 16;

    for (int c = 0; c < NC; c++) {
        if (c + NSTAGE - 1 < NC) CP_WAITN(); else CP_WAIT0();
        __syncthreads();
        if (c + NSTAGE - 1 < NC) { fill((c + NSTAGE - 1) % NSTAGE, c + NSTAGE - 1); CP_COMMIT(); }
        uint32_t st = sb + (c % NSTAGE) * ST_SIZE;

#pragma unroll
        for (int ks = 0; ks < 4; ks++) {
            uint32_t kb = ks * 32 + lkb;
            uint32_t ah[4][4], bh[2][4];
#pragma unroll
            for (int mi = 0; mi < 4; mi++) {
                uint32_t ro = (wm * 64 + mi * 16 + lrow) * 128 + kb;
                ldm4(ah[mi], st + A_OFF + SWZ(ro));
            }
#pragma unroll
            for (int nj = 0; nj < 2; nj++) {
                uint32_t ro = (wn * 32 + nj * 16 + lrow) * 128 + kb;
                ldm4(bh[nj], st + B_OFF + SWZ(ro));
            }
#pragma unroll
            for (int mi = 0; mi < 4; mi++)
#pragma unroll
                for (int ni = 0; ni < 4; ni++) {
                    int nj = ni >> 1, hf = ni & 1;
                    mma16816(A.v[mi][ni], ah[mi], bh[nj][hf], bh[nj][hf + 2]);
                }
        }
    }
}

// ---------------- GEMM1: h = relu(x @ w1 + b1) -> fp16 ----------------
__global__ __launch_bounds__(256, 2) void k_fmma1(const float* __restrict__ b1) {
    extern __shared__ char smem[];
    int row0 = blockIdx.y * BM;
    if (row0 >= g_off[NE]) return;
    int e = 0;
#pragma unroll
    for (int i = 0; i < NE - 1; i++) if (g_off[i + 1] <= row0) e = i + 1;
    int col0 = blockIdx.x * BN;
    uint32_t sb = (smem_u32(smem) + 1023) & ~1023u;
    int tid = threadIdx.x;

    Acc A;
#pragma unroll
    for (int i = 0; i < 4; i++)
#pragma unroll
        for (int j = 0; j < 4; j++)
#pragma unroll
            for (int k = 0; k < 4; k++) A.v[i][j][k] = 0.f;

    hmma_mainloop(sb, A,
                  g_xq + (size_t)row0 * DM, DM,
                  g_w1h + (size_t)e * DF * DM + (size_t)col0 * DM, DM,
                  DM / BK, tid);

    int wid = tid >> 5, L = tid & 31;
    int wm = wid & 1, wn = wid >> 1;
    const float* b1e = b1 + (size_t)e * DF;
#pragma unroll
    for (int mi = 0; mi < 4; mi++) {
        int r0 = row0 + wm * 64 + mi * 16 + (L >> 2);
#pragma unroll
        for (int ni = 0; ni < 4; ni++) {
            int col = col0 + wn * 32 + ni * 8 + (L & 3) * 2;
            float bb0 = b1e[col], bb1 = b1e[col + 1];
            float* a = A.v[mi][ni];
#pragma unroll
            for (int hrow = 0; hrow < 2; hrow++) {
                int row = r0 + hrow * 8;
                __half2 hp;
                hp.x = __float2half_rn(fmaxf(a[hrow * 2 + 0] + bb0, 0.f));
                hp.y = __float2half_rn(fmaxf(a[hrow * 2 + 1] + bb1, 0.f));
                *(__half2*)(g_hq + (size_t)row * DF + col) = hp;
            }
        }
    }
}

// ---------------- GEMM2: out[tok] += (h @ w2 + b2) * gate (fused combine) ----------------
__global__ __launch_bounds__(256, 2) void k_fmma2(const float* __restrict__ b2,
                                                  float* __restrict__ out) {
    extern __shared__ char smem[];
    int row0 = blockIdx.y * BM;
    if (row0 >= g_off[NE]) return;
    int e = 0;
#pragma unroll
    for (int i = 0; i < NE - 1; i++) if (g_off[i + 1] <= row0) e = i + 1;
    int col0 = blockIdx.x * BN;
    uint32_t sb = (smem_u32(smem) + 1023) & ~1023u;
    int tid = threadIdx.x;

    Acc A;
#pragma unroll
    for (int i = 0; i < 4; i++)
#pragma unroll
        for (int j = 0; j < 4; j++)
#pragma unroll
            for (int k = 0; k < 4; k++) A.v[i][j][k] = 0.f;

    hmma_mainloop(sb, A,
                  g_hq + (size_t)row0 * DF, DF,
                  g_w2h + (size_t)e * DM * DF + (size_t)col0 * DF, DF,
                  DF / BK, tid);

    int wid = tid >> 5, L = tid & 31;
    int wm = wid & 1, wn = wid >> 1;
    const float* b2e = b2 + (size_t)e * DM;
#pragma unroll
    for (int mi = 0; mi < 4; mi++) {
        int r0 = row0 + wm * 64 + mi * 16 + (L >> 2);
#pragma unroll
        for (int ni = 0; ni < 4; ni++) {
            int col = col0 + wn * 32 + ni * 8 + (L & 3) * 2;
            float bb0 = b2e[col], bb1 = b2e[col + 1];
            float* a = A.v[mi][ni];
#pragma unroll
            for (int hrow = 0; hrow < 2; hrow++) {
                int row = r0 + hrow * 8;
                int tok = g_atok[row];
                if (tok >= 0) {
                    float sc = g_aw[row];
                    float* o = out + (size_t)tok * DM + col;
                    atomicAdd(o,     (a[hrow * 2 + 0] + bb0) * sc);
                    atomicAdd(o + 1, (a[hrow * 2 + 1] + bb1) * sc);
                }
            }
        }
    }
}

// ---------------- launch ----------------
extern "C" void kernel_launch(void* const* d_in, const int* in_sizes, int n_in,
                              void* d_out, int out_size) {
    const float* x  = (const float*)d_in[0];
    const float* gw = (const float*)d_in[1];
    const float* gb = (const float*)d_in[2];
    const float* w1 = (const float*)d_in[3];
    const float* b1 = (const float*)d_in[4];
    const float* w2 = (const float*)d_in[5];
    const float* b2 = (const float*)d_in[6];
    float* out = (float*)d_out;

    cudaFuncSetAttribute(k_fmma1, cudaFuncAttributeMaxDynamicSharedMemorySize, SMEM_BYTES);
    cudaFuncSetAttribute(k_fmma2, cudaFuncAttributeMaxDynamicSharedMemorySize, SMEM_BYTES);

    k_init<<<(MAXROWS + 255) / 256, 256>>>();
    k_zero<<<NTOK * DM / 1024, 256>>>(out);
    k_gate<<<NTOK / 8, 256>>>(x, gw, gb);
    k_off<<<1, 1>>>();
    k_scatter<<<(NTOK + 255) / 256, 256>>>();
    k_actsplit<<<MAXROWS, 256>>>(x);
    k_wsplit_t<DM, DF, true><<<dim3(DF / 32, DM / 32, NE), dim3(32, 8)>>>(w1);
    k_wsplit_t<DF, DM, false><<<dim3(DM / 32, DF / 32, NE), dim3(32, 8)>>>(w2);
    k_fmma1<<<dim3(DF / BN, MT), 256, SMEM_BYTES>>>(b1);
    k_fmma2<<<dim3(DM / BN, MT), 256, SMEM_BYTES>>>(b2, out);
}

// round 11
// speedup vs baseline: 3.9330x; 1.0063x over previous
#include <cuda_runtime.h>
#include <cuda_fp16.h>
#include <math.h>
#include <stdint.h>

#define NTOK 8192
#define DM 1024
#define DF 4096
#define NE 8
#define BM 128
#define BN 128
#define BK 64
#define MAXROWS (NTOK*2 + NE*BM)   /* 17408 */
#define MT (MAXROWS/BM)            /* 136 */

// smem stage: A 16K + B 16K = 32KB; 3 stages -> 99KB total -> 2 CTAs/SM
#define A_OFF 0
#define B_OFF 16384
#define ST_SIZE 32768
#define NSTAGE 3
#define SMEM_BYTES (1024 + NSTAGE*ST_SIZE)   /* 99328 */

// ---------------- scratch (device globals: allocation-free) ----------------
__device__ __align__(16) __half g_xq[(size_t)MAXROWS * DM];
__device__ __align__(16) __half g_hq[(size_t)MAXROWS * DF];
__device__ __align__(16) __half g_w1h[(size_t)NE * DF * DM];
__device__ __align__(16) __half g_w2h[(size_t)NE * DM * DF];
__device__ int   g_atok[MAXROWS];
__device__ float g_aw[MAXROWS];
__device__ int   g_t2e[NTOK * 2];
__device__ float g_t2w[NTOK * 2];
__device__ int   g_cnt[NE];
__device__ int   g_fill[NE];
__device__ int   g_off[NE + 1];

// ---------------- helpers ----------------
__device__ __forceinline__ uint32_t smem_u32(const void* p) {
    uint32_t a;
    asm("{ .reg .u64 t; cvta.to.shared.u64 t, %1; cvt.u32.u64 %0, t; }" : "=r"(a) : "l"(p));
    return a;
}
#define SWZ(x) ((uint32_t)(x) ^ ((((uint32_t)(x)) >> 3) & 0x70))

__device__ __forceinline__ void cp16(uint32_t dst, const void* src) {
    asm volatile("cp.async.cg.shared.global [%0], [%1], 16;" :: "r"(dst), "l"(src));
}
#define CP_COMMIT() asm volatile("cp.async.commit_group;" ::: "memory")
#define CP_WAITN()  asm volatile("cp.async.wait_group %0;" :: "n"(NSTAGE - 2) : "memory")
#define CP_WAIT0()  asm volatile("cp.async.wait_group 0;" ::: "memory")

__device__ __forceinline__ void ldm4(uint32_t* r, uint32_t addr) {
    asm volatile("ldmatrix.sync.aligned.m8n8.x4.shared.b16 {%0,%1,%2,%3}, [%4];"
        : "=r"(r[0]), "=r"(r[1]), "=r"(r[2]), "=r"(r[3]) : "r"(addr));
}
__device__ __forceinline__ void mma16816(float* c, const uint32_t* a, uint32_t b0, uint32_t b1) {
    asm volatile("mma.sync.aligned.m16n8k16.row.col.f32.f16.f16.f32 "
        "{%0,%1,%2,%3}, {%4,%5,%6,%7}, {%8,%9}, {%0,%1,%2,%3};"
        : "+f"(c[0]), "+f"(c[1]), "+f"(c[2]), "+f"(c[3])
        : "r"(a[0]), "r"(a[1]), "r"(a[2]), "r"(a[3]), "r"(b0), "r"(b1));
}

// ---------------- init ----------------
__global__ void k_init() {
    int i = blockIdx.x * blockDim.x + threadIdx.x;
    if (i < MAXROWS) g_atok[i] = -1;
    if (i < NE) { g_cnt[i] = 0; g_fill[i] = 0; }
}

__global__ void k_zero(float* __restrict__ out) {
    ((float4*)out)[blockIdx.x * 256 + threadIdx.x] = make_float4(0.f, 0.f, 0.f, 0.f);
}

// ---------------- gating ----------------
__global__ __launch_bounds__(256) void k_gate(const float* __restrict__ x,
                                              const float* __restrict__ gw,
                                              const float* __restrict__ gb) {
    __shared__ float sgw[DM * NE];
    int tid = threadIdx.x;
    for (int i = tid; i < DM * NE; i += 256) sgw[i] = gw[i];
    __syncthreads();
    int warp = tid >> 5, lane = tid & 31;
    int t = blockIdx.x * 8 + warp;
    const float* xr = x + (size_t)t * DM;
    float acc[NE];
#pragma unroll
    for (int e = 0; e < NE; e++) acc[e] = 0.f;
    for (int d = lane; d < DM; d += 32) {
        float xv = xr[d];
#pragma unroll
        for (int e = 0; e < NE; e++) acc[e] = fmaf(xv, sgw[d * NE + e], acc[e]);
    }
#pragma unroll
    for (int off = 16; off; off >>= 1)
#pragma unroll
        for (int e = 0; e < NE; e++) acc[e] += __shfl_xor_sync(0xFFFFFFFFu, acc[e], off);
    if (lane == 0) {
        float lg[NE], m = -1e30f;
#pragma unroll
        for (int e = 0; e < NE; e++) { lg[e] = acc[e] + gb[e]; m = fmaxf(m, lg[e]); }
        float ex[NE], s = 0.f;
#pragma unroll
        for (int e = 0; e < NE; e++) { ex[e] = expf(lg[e] - m); s += ex[e]; }
        int e0 = 0;
#pragma unroll
        for (int e = 1; e < NE; e++) if (ex[e] > ex[e0]) e0 = e;
        int e1 = (e0 == 0) ? 1 : 0;
#pragma unroll
        for (int e = 0; e < NE; e++) if (e != e0 && ex[e] > ex[e1]) e1 = e;
        float inv = 1.f / s;
        g_t2e[2 * t] = e0;     g_t2w[2 * t] = ex[e0] * inv;
        g_t2e[2 * t + 1] = e1; g_t2w[2 * t + 1] = ex[e1] * inv;
        atomicAdd(&g_cnt[e0], 1);
        atomicAdd(&g_cnt[e1], 1);
    }
}

__global__ void k_off() {
    g_off[0] = 0;
    for (int e = 0; e < NE; e++)
        g_off[e + 1] = g_off[e] + (((g_cnt[e] + BM - 1) / BM) * BM);
}

__global__ void k_scatter() {
    int t = blockIdx.x * blockDim.x + threadIdx.x;
    if (t >= NTOK) return;
#pragma unroll
    for (int r = 0; r < 2; r++) {
        int e = g_t2e[2 * t + r];
        int p = atomicAdd(&g_fill[e], 1);
        int s = g_off[e] + p;
        g_atok[s] = t;
        g_aw[s] = g_t2w[2 * t + r];
    }
}

// ---------------- gather + fp16 activations ----------------
__global__ __launch_bounds__(256) void k_actsplit(const float* __restrict__ x) {
    int slot = blockIdx.x;
    int tok = g_atok[slot];
    int t4 = threadIdx.x;
    float4 v = make_float4(0.f, 0.f, 0.f, 0.f);
    if (tok >= 0) v = ((const float4*)(x + (size_t)tok * DM))[t4];
    __half2 p0; p0.x = __float2half_rn(v.x); p0.y = __float2half_rn(v.y);
    __half2 p1; p1.x = __float2half_rn(v.z); p1.y = __float2half_rn(v.w);
    size_t base = (size_t)slot * DM + t4 * 4;
    *(__half2*)(g_xq + base)     = p0;
    *(__half2*)(g_xq + base + 2) = p1;
}

// ---------------- transpose + fp16 weights ----------------
// src [e][K][N] (N contiguous) -> dst global [e][N][K] (K contiguous).
// Output referenced as device global INSIDE device code (round-3 lesson).
template <int K, int N, bool IS_W1>
__global__ __launch_bounds__(256) void k_wsplit_t(const float* __restrict__ w) {
    __shared__ float tile[32][33];
    int e = blockIdx.z;
    int n0 = blockIdx.x * 32, k0 = blockIdx.y * 32;
    int tx = threadIdx.x, ty = threadIdx.y;
    const float* we = w + (size_t)e * K * N;
    for (int i = ty; i < 32; i += 8)
        tile[i][tx] = we[(size_t)(k0 + i) * N + n0 + tx];
    __syncthreads();
    __half* ohe = (IS_W1 ? g_w1h : g_w2h) + (size_t)e * N * K;
    for (int i = ty; i < 32; i += 8)
        ohe[(size_t)(n0 + i) * K + k0 + tx] = __float2half_rn(tile[tx][i]);
}

// ================= HMMA mainloop: single fp16 pass, 3-stage, 2 CTAs/SM =================
struct Acc { float v[4][4][4]; };   // [mi][ni][frag]

__device__ __forceinline__ void hmma_mainloop(
    uint32_t sb, Acc& A,
    const __half* Ap, int astride,
    const __half* Bp, int bstride,
    int NC, int tid)
{
    int wid = tid >> 5, L = tid & 31;
    int wm = wid & 1, wn = wid >> 1;   // 2 x 4 warp grid, warp tile 64x32

    int fr = tid & 127;                // fill row
    int hb = (tid >> 7) * 64;          // byte half within 128B row

    auto fill = [&](int s, int c) {
        uint32_t st = sb + s * ST_SIZE;
        const char* pa = (const char*)(Ap + (size_t)fr * astride + c * BK) + hb;
        const char* pb = (const char*)(Bp + (size_t)fr * bstride + c * BK) + hb;
        uint32_t rb = fr * 128 + hb;
#pragma unroll
        for (int j = 0; j < 4; j++) {
            uint32_t o = SWZ(rb + j * 16);
            cp16(st + A_OFF + o, pa + j * 16);
            cp16(st + B_OFF + o, pb + j * 16);
        }
    };

#pragma unroll
    for (int p = 0; p < NSTAGE - 1; p++) { fill(p, p); CP_COMMIT(); }

    int lrow = L & 15;
    int lkb = (L >> 4) * 16;

    for (int c = 0; c < NC; c++) {
        if (c + NSTAGE - 1 < NC) CP_WAITN(); else CP_WAIT0();
        __syncthreads();
        if (c + NSTAGE - 1 < NC) { fill((c + NSTAGE - 1) % NSTAGE, c + NSTAGE - 1); CP_COMMIT(); }
        uint32_t st = sb + (c % NSTAGE) * ST_SIZE;

#pragma unroll
        for (int ks = 0; ks < 4; ks++) {
            uint32_t kb = ks * 32 + lkb;
            uint32_t ah[4][4], bh[2][4];
#pragma unroll
            for (int mi = 0; mi < 4; mi++) {
                uint32_t ro = (wm * 64 + mi * 16 + lrow) * 128 + kb;
                ldm4(ah[mi], st + A_OFF + SWZ(ro));
            }
#pragma unroll
            for (int nj = 0; nj < 2; nj++) {
                uint32_t ro = (wn * 32 + nj * 16 + lrow) * 128 + kb;
                ldm4(bh[nj], st + B_OFF + SWZ(ro));
            }
#pragma unroll
            for (int mi = 0; mi < 4; mi++)
#pragma unroll
                for (int ni = 0; ni < 4; ni++) {
                    int nj = ni >> 1, hf = ni & 1;
                    mma16816(A.v[mi][ni], ah[mi], bh[nj][hf], bh[nj][hf + 2]);
                }
        }
    }
}

// ---------------- GEMM1: h = relu(x @ w1 + b1) -> fp16 ----------------
__global__ __launch_bounds__(256, 2) void k_fmma1(const float* __restrict__ b1) {
    extern __shared__ char smem[];
    int row0 = blockIdx.y * BM;
    if (row0 >= g_off[NE]) return;
    int e = 0;
#pragma unroll
    for (int i = 0; i < NE - 1; i++) if (g_off[i + 1] <= row0) e = i + 1;
    int col0 = blockIdx.x * BN;
    uint32_t sb = (smem_u32(smem) + 1023) & ~1023u;
    int tid = threadIdx.x;

    Acc A;
#pragma unroll
    for (int i = 0; i < 4; i++)
#pragma unroll
        for (int j = 0; j < 4; j++)
#pragma unroll
            for (int k = 0; k < 4; k++) A.v[i][j][k] = 0.f;

    hmma_mainloop(sb, A,
                  g_xq + (size_t)row0 * DM, DM,
                  g_w1h + (size_t)e * DF * DM + (size_t)col0 * DM, DM,
                  DM / BK, tid);

    int wid = tid >> 5, L = tid & 31;
    int wm = wid & 1, wn = wid >> 1;
    const float* b1e = b1 + (size_t)e * DF;
#pragma unroll
    for (int mi = 0; mi < 4; mi++) {
        int r0 = row0 + wm * 64 + mi * 16 + (L >> 2);
#pragma unroll
        for (int ni = 0; ni < 4; ni++) {
            int col = col0 + wn * 32 + ni * 8 + (L & 3) * 2;
            float bb0 = b1e[col], bb1 = b1e[col + 1];
            float* a = A.v[mi][ni];
#pragma unroll
            for (int hrow = 0; hrow < 2; hrow++) {
                int row = r0 + hrow * 8;
                __half2 hp;
                hp.x = __float2half_rn(fmaxf(a[hrow * 2 + 0] + bb0, 0.f));
                hp.y = __float2half_rn(fmaxf(a[hrow * 2 + 1] + bb1, 0.f));
                *(__half2*)(g_hq + (size_t)row * DF + col) = hp;
            }
        }
    }
}

// ---------------- GEMM2: out[tok] += (h @ w2 + b2) * gate (fused combine) ----------------
__global__ __launch_bounds__(256, 2) void k_fmma2(const float* __restrict__ b2,
                                                  float* __restrict__ out) {
    extern __shared__ char smem[];
    int row0 = blockIdx.y * BM;
    if (row0 >= g_off[NE]) return;
    int e = 0;
#pragma unroll
    for (int i = 0; i < NE - 1; i++) if (g_off[i + 1] <= row0) e = i + 1;
    int col0 = blockIdx.x * BN;
    uint32_t sb = (smem_u32(smem) + 1023) & ~1023u;
    int tid = threadIdx.x;

    Acc A;
#pragma unroll
    for (int i = 0; i < 4; i++)
#pragma unroll
        for (int j = 0; j < 4; j++)
#pragma unroll
            for (int k = 0; k < 4; k++) A.v[i][j][k] = 0.f;

    hmma_mainloop(sb, A,
                  g_hq + (size_t)row0 * DF, DF,
                  g_w2h + (size_t)e * DM * DF + (size_t)col0 * DF, DF,
                  DF / BK, tid);

    int wid = tid >> 5, L = tid & 31;
    int wm = wid & 1, wn = wid >> 1;
    const float* b2e = b2 + (size_t)e * DM;
#pragma unroll
    for (int mi = 0; mi < 4; mi++) {
        int r0 = row0 + wm * 64 + mi * 16 + (L >> 2);
#pragma unroll
        for (int ni = 0; ni < 4; ni++) {
            int col = col0 + wn * 32 + ni * 8 + (L & 3) * 2;
            float bb0 = b2e[col], bb1 = b2e[col + 1];
            float* a = A.v[mi][ni];
#pragma unroll
            for (int hrow = 0; hrow < 2; hrow++) {
                int row = r0 + hrow * 8;
                int tok = g_atok[row];
                if (tok >= 0) {
                    float sc = g_aw[row];
                    float* o = out + (size_t)tok * DM + col;
                    atomicAdd(o,     (a[hrow * 2 + 0] + bb0) * sc);
                    atomicAdd(o + 1, (a[hrow * 2 + 1] + bb1) * sc);
                }
            }
        }
    }
}

// ---------------- launch ----------------
extern "C" void kernel_launch(void* const* d_in, const int* in_sizes, int n_in,
                              void* d_out, int out_size) {
    const float* x  = (const float*)d_in[0];
    const float* gw = (const float*)d_in[1];
    const float* gb = (const float*)d_in[2];
    const float* w1 = (const float*)d_in[3];
    const float* b1 = (const float*)d_in[4];
    const float* w2 = (const float*)d_in[5];
    const float* b2 = (const float*)d_in[6];
    float* out = (float*)d_out;

    // statics created on the FIRST call, which the harness runs uncaptured
    // (correctness pass) before graph capture; reused as-is during capture.
    // No device memory is allocated here.
    static cudaStream_t sB = 0;
    static cudaEvent_t evF = 0, evJ = 0;
    static bool inited = false;
    if (!inited) {
        cudaStreamCreateWithFlags(&sB, cudaStreamNonBlocking);
        cudaEventCreateWithFlags(&evF, cudaEventDisableTiming);
        cudaEventCreateWithFlags(&evJ, cudaEventDisableTiming);
        cudaFuncSetAttribute(k_fmma1, cudaFuncAttributeMaxDynamicSharedMemorySize, SMEM_BYTES);
        cudaFuncSetAttribute(k_fmma2, cudaFuncAttributeMaxDynamicSharedMemorySize, SMEM_BYTES);
        inited = true;
    }

    // ---- fork: weight conversion + output zeroing on side stream ----
    cudaEventRecord(evF, 0);
    cudaStreamWaitEvent(sB, evF, 0);
    k_zero<<<NTOK * DM / 1024, 256, 0, sB>>>(out);
    k_wsplit_t<DM, DF, true><<<dim3(DF / 32, DM / 32, NE), dim3(32, 8), 0, sB>>>(w1);
    k_wsplit_t<DF, DM, false><<<dim3(DM / 32, DF / 32, NE), dim3(32, 8), 0, sB>>>(w2);
    cudaEventRecord(evJ, sB);

    // ---- main chain: gating / routing / activation gather ----
    k_init<<<(MAXROWS + 255) / 256, 256>>>();
    k_gate<<<NTOK / 8, 256>>>(x, gw, gb);
    k_off<<<1, 1>>>();
    k_scatter<<<(NTOK + 255) / 256, 256>>>();
    k_actsplit<<<MAXROWS, 256>>>(x);

    // ---- join, then GEMMs ----
    cudaStreamWaitEvent(0, evJ, 0);
    k_fmma1<<<dim3(DF / BN, MT), 256, SMEM_BYTES>>>(b1);
    k_fmma2<<<dim3(DM / BN, MT), 256, SMEM_BYTES>>>(b2, out);
}